// round 14
// baseline (speedup 1.0000x reference)
#include <cuda_runtime.h>
#include <cuda_bf16.h>
#include <stdint.h>

#define THREADS 256
#define TILE 128
#define NPER 50000

// Z1/Z2: 4 k-planes (each covers 2 k-steps = 32 channels). Plane = 128 points x 64B (+64 pad).
#define PLANE_BYTES 8256
#define ZBUF_FLOATS (4 * PLANE_BYTES / 4)    // 8256 floats each
#define YBUF 512                              // 128 points x float4

// smem floats: Z1 + Z2 + y0/y/k1/k2 + h2b/g2b
#define SMEM_FLOATS (2 * ZBUF_FLOATS + 4 * YBUF + 256)

// Packed, fragment-ordered bf16 A-operands (g2 pre-scaled by 0.5).
__device__ uint4 g_Ah[256 * 8];
__device__ uint4 g_Ag[256 * 8];
// Out-layer A fragments (warp-invariant): [lane 0..31][s 0..7] = (a0, a2)
__device__ uint2 g_Ao[32 * 8];

static __device__ __forceinline__ float tanha(float x) {
    float r;
    asm("tanh.approx.f32 %0, %1;" : "=f"(r) : "f"(x));
    return r;
}
// sigmoid from HALF-SCALED preactivation
static __device__ __forceinline__ float fsig2(float x_half) {
    return fmaf(tanha(x_half), 0.5f, 0.5f);
}
static __device__ __forceinline__ uint32_t pack_bf2(float lo, float hi) {
    __nv_bfloat162 v = __floats2bfloat162_rn(lo, hi);
    return *(uint32_t*)&v;
}
static __device__ __forceinline__ void mma16(float d[4], const uint32_t a[4],
                                             uint32_t b0, uint32_t b1) {
    asm volatile(
        "mma.sync.aligned.m16n8k16.row.col.f32.bf16.bf16.f32 "
        "{%0,%1,%2,%3}, {%4,%5,%6,%7}, {%8,%9}, {%0,%1,%2,%3};\n"
        : "+f"(d[0]), "+f"(d[1]), "+f"(d[2]), "+f"(d[3])
        : "r"(a[0]), "r"(a[1]), "r"(a[2]), "r"(a[3]), "r"(b0), "r"(b1));
}
// out-GEMM mma: a1 = a3 = 0 (rows 8..15 of OW are zero)
static __device__ __forceinline__ void mma16o(float d[4], uint32_t a0, uint32_t a2,
                                              uint32_t b0, uint32_t b1) {
    asm volatile(
        "mma.sync.aligned.m16n8k16.row.col.f32.bf16.bf16.f32 "
        "{%0,%1,%2,%3}, {%4,%5,%6,%7}, {%8,%9}, {%0,%1,%2,%3};\n"
        : "+f"(d[0]), "+f"(d[1]), "+f"(d[2]), "+f"(d[3])
        : "r"(a0), "r"(0u), "r"(a2), "r"(0u), "r"(b0), "r"(b1));
}

// ---- prep kernel: pack A fragments (h2, g2 scaled, out_w) ----
__global__ void prep_kernel(const float* __restrict__ h2w,
                            const float* __restrict__ g2w,
                            const float* __restrict__ outw) {
    int idx = blockIdx.x * blockDim.x + threadIdx.x;
    if (idx < 4096) {
        int s    = idx & 7;
        int wl   = (idx >> 3) & 255;
        int gemm = idx >> 11;
        int warp = wl >> 5, lane = wl & 31;
        int g = lane >> 2, tg = lane & 3;
        int r0 = warp * 16 + g, k0 = 16 * s + 2 * tg;
        const float* w = gemm ? g2w : h2w;
        float sc = gemm ? 0.5f : 1.0f;
        uint4 v;
        v.x = pack_bf2(sc * w[r0 * 128 + k0],           sc * w[r0 * 128 + k0 + 1]);
        v.y = pack_bf2(sc * w[(r0 + 8) * 128 + k0],     sc * w[(r0 + 8) * 128 + k0 + 1]);
        v.z = pack_bf2(sc * w[r0 * 128 + k0 + 8],       sc * w[r0 * 128 + k0 + 9]);
        v.w = pack_bf2(sc * w[(r0 + 8) * 128 + k0 + 8], sc * w[(r0 + 8) * 128 + k0 + 9]);
        (gemm ? g_Ag : g_Ah)[wl * 8 + s] = v;
    } else if (idx < 4096 + 256) {
        int i2 = idx - 4096;
        int s = i2 & 7, lane = i2 >> 3;
        int g = lane >> 2, tg = lane & 3;
        int k0 = 16 * s + 2 * tg;
        uint2 v = make_uint2(0u, 0u);
        if (g < 3) {
            v.x = pack_bf2(outw[g * 128 + k0],     outw[g * 128 + k0 + 1]);
            v.y = pack_bf2(outw[g * 128 + k0 + 8], outw[g * 128 + k0 + 9]);
        }
        g_Ao[lane * 8 + s] = v;
    }
}

struct Bufs {
    char  *Z1, *Z2;
    float *h2b, *g2b;
};
struct L1W {
    float wh0[4], wg0[4], bh0, bg0;   // wg/bg pre-scaled by 0.5
    float wh1[4], wg1[4], bh1, bg1;
};

// One field evaluation; STAGE selects fused RK update in the out-GEMM epilogue.
template <int STAGE>
static __device__ __forceinline__ void field_eval(
    float t, float* __restrict__ yb,
    float* __restrict__ y0b, float* __restrict__ k1b, float* __restrict__ k2b,
    const Bufs& B, const L1W& W, char* __restrict__ z1wr, char* __restrict__ z2wr,
    const uint32_t (&Ah)[8][4], const uint32_t (&Ag)[8][4], float obg,
    int tid, int warp, int lane, int p0, float* __restrict__ yout, int P)
{
    const int g = lane >> 2, tg = lane & 3;

    // ---- layer 1 (4 -> 128, gated) ----
    {
        const int q = warp >> 1;
        const float bh0t = W.bh0 + W.wh0[3] * t;
        const float bg0t = W.bg0 + W.wg0[3] * t;
        const float bh1t = W.bh1 + W.wh1[3] * t;
        const float bg1t = W.bg1 + W.wg1[3] * t;
        #pragma unroll 4
        for (int i = 0; i < 32; ++i) {
            const int p = 4 * i + q;
            const float4 Y = *(const float4*)(yb + 4 * p);   // broadcast LDS.128
            float h0 = fmaf(W.wh0[0], Y.x, fmaf(W.wh0[1], Y.y, fmaf(W.wh0[2], Y.z, bh0t)));
            float g0 = fmaf(W.wg0[0], Y.x, fmaf(W.wg0[1], Y.y, fmaf(W.wg0[2], Y.z, bg0t)));
            float h1 = fmaf(W.wh1[0], Y.x, fmaf(W.wh1[1], Y.y, fmaf(W.wh1[2], Y.z, bh1t)));
            float g1 = fmaf(W.wg1[0], Y.x, fmaf(W.wg1[1], Y.y, fmaf(W.wg1[2], Y.z, bg1t)));
            float z0 = fmaxf(h0 * fsig2(g0), 0.0f);
            float z1 = fmaxf(h1 * fsig2(g1), 0.0f);
            *(uint32_t*)(z1wr + p * 64) = pack_bf2(z0, z1);
        }
    }
    __syncthreads();

    // ---- layer 2: two bf16 GEMMs; gate-combine in regs; z2 -> Z2 (B-fragment layout) ----
    {
        const int row = warp * 16 + g;
        const float bh0 = B.h2b[row], bh1 = B.h2b[row + 8];
        const float bg0 = B.g2b[row], bg1 = B.g2b[row + 8];
        const bool evn = ((lane & 4) == 0);

        #pragma unroll 2
        for (int n0 = 0; n0 < 128; n0 += 8) {
            const char* rowp = B.Z1 + (n0 + g) * 64 + tg * 16;
            uint4 f0 = *(const uint4*)(rowp);
            uint4 f1 = *(const uint4*)(rowp + PLANE_BYTES);
            uint4 f2 = *(const uint4*)(rowp + 2 * PLANE_BYTES);
            uint4 f3 = *(const uint4*)(rowp + 3 * PLANE_BYTES);
            float dh[4] = {bh0, bh0, bh1, bh1};
            float dg[4] = {bg0, bg0, bg1, bg1};
            mma16(dh, Ah[0], f0.x, f0.y);  mma16(dg, Ag[0], f0.x, f0.y);
            mma16(dh, Ah[1], f0.z, f0.w);  mma16(dg, Ag[1], f0.z, f0.w);
            mma16(dh, Ah[2], f1.x, f1.y);  mma16(dg, Ag[2], f1.x, f1.y);
            mma16(dh, Ah[3], f1.z, f1.w);  mma16(dg, Ag[3], f1.z, f1.w);
            mma16(dh, Ah[4], f2.x, f2.y);  mma16(dg, Ag[4], f2.x, f2.y);
            mma16(dh, Ah[5], f2.z, f2.w);  mma16(dg, Ag[5], f2.z, f2.w);
            mma16(dh, Ah[6], f3.x, f3.y);  mma16(dg, Ag[6], f3.x, f3.y);
            mma16(dh, Ah[7], f3.z, f3.w);  mma16(dg, Ag[7], f3.z, f3.w);

            float z00 = fmaxf(dh[0] * fsig2(dg[0]), 0.f);
            float z01 = fmaxf(dh[1] * fsig2(dg[1]), 0.f);
            float z10 = fmaxf(dh[2] * fsig2(dg[2]), 0.f);
            float z11 = fmaxf(dh[3] * fsig2(dg[3]), 0.f);

            // pair adjacent channels (g <-> g^1) and store z2 in B-fragment layout
            float rz00 = __shfl_xor_sync(0xffffffffu, z00, 4);
            float rz01 = __shfl_xor_sync(0xffffffffu, z01, 4);
            float rz10 = __shfl_xor_sync(0xffffffffu, z10, 4);
            float rz11 = __shfl_xor_sync(0xffffffffu, z11, 4);
            float loA = evn ? z00 : rz01,  hiA = evn ? rz00 : z01;
            float loB = evn ? z10 : rz11,  hiB = evn ? rz10 : z11;
            int   c   = n0 + 2 * tg + (evn ? 0 : 1);
            *(uint2*)(z2wr + c * 64) = make_uint2(pack_bf2(loA, hiA), pack_bf2(loB, hiB));
        }
    }

    // prefetch out-layer A fragments (latency hidden by the barrier)
    uint2 ao[8];
    {
        const uint2* p = g_Ao + lane * 8;
        #pragma unroll
        for (int s = 0; s < 8; ++s) ao[s] = p[s];
    }
    __syncthreads();

    // ---- out-GEMM: D[16(3 used) x 16 pts per warp] = OW x Z2, fused tanh + RK ----
    const float third = 1.0f / 3.0f;
    #pragma unroll
    for (int tile = 0; tile < 2; ++tile) {
        const int nc = warp * 16 + tile * 8;
        const char* rowp = B.Z2 + (nc + g) * 64 + tg * 16;
        uint4 f0 = *(const uint4*)(rowp);
        uint4 f1 = *(const uint4*)(rowp + PLANE_BYTES);
        uint4 f2 = *(const uint4*)(rowp + 2 * PLANE_BYTES);
        uint4 f3 = *(const uint4*)(rowp + 3 * PLANE_BYTES);
        float d[4] = {0.f, 0.f, 0.f, 0.f};
        mma16o(d, ao[0].x, ao[0].y, f0.x, f0.y);
        mma16o(d, ao[1].x, ao[1].y, f0.z, f0.w);
        mma16o(d, ao[2].x, ao[2].y, f1.x, f1.y);
        mma16o(d, ao[3].x, ao[3].y, f1.z, f1.w);
        mma16o(d, ao[4].x, ao[4].y, f2.x, f2.y);
        mma16o(d, ao[5].x, ao[5].y, f2.z, f2.w);
        mma16o(d, ao[6].x, ao[6].y, f3.x, f3.y);
        mma16o(d, ao[7].x, ao[7].y, f3.z, f3.w);

        if (g < 3) {
            #pragma unroll
            for (int colh = 0; colh < 2; ++colh) {
                const int pl = nc + 2 * tg + colh;
                const int j  = 4 * pl + g;
                float k = tanha(d[colh] + obg) * 0.5f;
                if (STAGE == 0) {
                    k1b[j] = k;
                    yb[j]  = y0b[j] + k * third;
                } else if (STAGE == 1) {
                    float a = k1b[j];
                    k2b[j] = k;
                    yb[j]  = y0b[j] + (k - a * third);
                } else if (STAGE == 2) {
                    float a = k1b[j], b2 = k2b[j];
                    yb[j]  = y0b[j] + (a - b2 + k);
                    k1b[j] = a + 3.0f * (b2 + k);   // fold k1 + 3*(k2+k3)
                } else {
                    int pg = p0 + pl;
                    if (pg < P) {
                        int b = pg / NPER, n = pg - b * NPER;
                        yout[(b * 3 + g) * NPER + n] = y0b[j] + (k1b[j] + k) * 0.125f;
                    }
                }
            }
        }
    }
    if (STAGE < 3) __syncthreads();
}

__global__ void __launch_bounds__(THREADS, 2)
node_kernel(const float* __restrict__ x0,
            const float* __restrict__ h1_w, const float* __restrict__ h1_b,
            const float* __restrict__ g1_w, const float* __restrict__ g1_b,
            const float* __restrict__ h2_b_, const float* __restrict__ g2_b_,
            const float* __restrict__ out_b,
            float* __restrict__ yout, int P)
{
    extern __shared__ float sm[];
    Bufs B;
    B.Z1  = (char*)sm;
    B.Z2  = (char*)sm + 4 * PLANE_BYTES;
    float* y0b = sm + 2 * ZBUF_FLOATS;
    float* yb  = y0b + YBUF;
    float* k1b = yb  + YBUF;
    float* k2b = k1b + YBUF;
    B.h2b = k2b + YBUF;
    B.g2b = B.h2b + 128;

    const int tid  = threadIdx.x;
    const int warp = tid >> 5;
    const int lane = tid & 31;
    const int g    = lane >> 2;

    // stage biases into shared (g2 bias pre-scaled by 0.5)
    for (int i = tid; i < 128; i += THREADS) {
        B.h2b[i] = h2_b_[i];
        B.g2b[i] = 0.5f * g2_b_[i];
    }
    const float obg = (g < 3) ? out_b[g] : 0.0f;

    // this thread's Z1 write pointer (word = channels 2w, 2w+1)
    const int w = ((warp & 1) << 5) | lane;
    char* z1wr = B.Z1 + (w >> 4) * PLANE_BYTES
               + (w & 3) * 16 + ((w >> 3) & 1) * 8 + ((w >> 2) & 1) * 4;
    // Z2 write pointer for the L2 epilogue (add c*64 per store)
    char* z2wr = B.Z2 + (warp >> 1) * PLANE_BYTES + (g >> 1) * 16 + (warp & 1) * 8;

    // layer-1 weights (gate path pre-scaled by 0.5)
    L1W W;
    {
        const int c0 = 2 * w, c1 = 2 * w + 1;
        #pragma unroll
        for (int j = 0; j < 4; ++j) {
            W.wh0[j] = h1_w[c0 * 4 + j];  W.wg0[j] = 0.5f * g1_w[c0 * 4 + j];
            W.wh1[j] = h1_w[c1 * 4 + j];  W.wg1[j] = 0.5f * g1_w[c1 * 4 + j];
        }
        W.bh0 = h1_b[c0]; W.bg0 = 0.5f * g1_b[c0];
        W.bh1 = h1_b[c1]; W.bg1 = 0.5f * g1_b[c1];
    }

    // A fragments: vector loads from prep-packed buffers
    uint32_t Ah[8][4], Ag[8][4];
    {
        const uint4* ph = g_Ah + tid * 8;
        const uint4* pg = g_Ag + tid * 8;
        #pragma unroll
        for (int s = 0; s < 8; ++s) {
            uint4 vh = ph[s], vg = pg[s];
            Ah[s][0] = vh.x; Ah[s][1] = vh.y; Ah[s][2] = vh.z; Ah[s][3] = vh.w;
            Ag[s][0] = vg.x; Ag[s][1] = vg.y; Ag[s][2] = vg.z; Ag[s][3] = vg.w;
        }
    }

    // load y0 (x0) for this block's 128 points into [p][4] layout
    const int p0 = blockIdx.x * TILE;
    for (int i = tid; i < 4 * TILE; i += THREADS) {
        int pl = i >> 2, c = i & 3;
        int pg = p0 + pl;
        float v = 0.f;
        if (c < 3 && pg < P) {
            int b = pg / NPER, n = pg - b * NPER;
            v = x0[(b * 3 + c) * NPER + n];
        }
        y0b[i] = v; yb[i] = v;
    }
    __syncthreads();

    const float third = 1.0f / 3.0f;

    // RK4 3/8 rule (RK updates fused into the out-GEMM epilogue)
    field_eval<0>(0.0f,         yb, y0b, k1b, k2b, B, W, z1wr, z2wr, Ah, Ag, obg,
                  tid, warp, lane, p0, yout, P);
    field_eval<1>(third,        yb, y0b, k1b, k2b, B, W, z1wr, z2wr, Ah, Ag, obg,
                  tid, warp, lane, p0, yout, P);
    field_eval<2>(third * 2.0f, yb, y0b, k1b, k2b, B, W, z1wr, z2wr, Ah, Ag, obg,
                  tid, warp, lane, p0, yout, P);
    field_eval<3>(1.0f,         yb, y0b, k1b, k2b, B, W, z1wr, z2wr, Ah, Ag, obg,
                  tid, warp, lane, p0, yout, P);
}

extern "C" void kernel_launch(void* const* d_in, const int* in_sizes, int n_in,
                              void* d_out, int out_size) {
    const float* x0    = (const float*)d_in[0];
    const float* h1_w  = (const float*)d_in[1];
    const float* h1_b  = (const float*)d_in[2];
    const float* g1_w  = (const float*)d_in[3];
    const float* g1_b  = (const float*)d_in[4];
    const float* h2_w  = (const float*)d_in[5];
    const float* h2_b  = (const float*)d_in[6];
    const float* g2_w  = (const float*)d_in[7];
    const float* g2_b  = (const float*)d_in[8];
    const float* out_w = (const float*)d_in[9];
    const float* out_b = (const float*)d_in[10];
    float* yout = (float*)d_out;

    const int P = in_sizes[0] / 3;                 // total points = B*N
    const int blocks = (P + TILE - 1) / TILE;      // 3125
    const size_t smem = SMEM_FLOATS * sizeof(float);

    prep_kernel<<<9, 512>>>(h2_w, g2_w, out_w);

    cudaFuncSetAttribute(node_kernel, cudaFuncAttributeMaxDynamicSharedMemorySize, (int)smem);
    node_kernel<<<blocks, THREADS, smem>>>(x0, h1_w, h1_b, g1_w, g1_b,
                                           h2_b, g2_b, out_b, yout, P);
}